// round 3
// baseline (speedup 1.0000x reference)
#include <cuda_runtime.h>
#include <math.h>
#include <stdint.h>

#define HW 4096
#define CC 768
#define NHEADS 12
#define HD 64
#define SP 68   // smem row stride in floats (272B, 16B-aligned, bank-spreading)

// ---------------- scratch ----------------------------------------------------
__device__ float g_Q[(size_t)NHEADS * HW * HD];
__device__ float g_K[(size_t)NHEADS * HW * HD];
__device__ float g_V[(size_t)NHEADS * HW * HD];
__device__ float g_relh[(size_t)NHEADS * HD * HW];  // TRANSPOSED: [head][kh][tok]
__device__ float g_relw[(size_t)NHEADS * HW * HD];  // [head][tok][kw]
__device__ float g_att[(size_t)HW * CC];

// ---------------- helpers ----------------------------------------------------
__device__ __forceinline__ float f2tf(float x) {
    uint32_t u;
    asm("cvt.rna.tf32.f32 %0, %1;" : "=r"(u) : "f"(x));
    return __uint_as_float(u);
}

__device__ __forceinline__ void mma8(float* c,
                                     uint32_t a0, uint32_t a1, uint32_t a2, uint32_t a3,
                                     uint32_t b0, uint32_t b1) {
    asm volatile(
        "mma.sync.aligned.m16n8k8.row.col.f32.tf32.tf32.f32 "
        "{%0,%1,%2,%3}, {%4,%5,%6,%7}, {%8,%9}, {%0,%1,%2,%3};\n"
        : "+f"(c[0]), "+f"(c[1]), "+f"(c[2]), "+f"(c[3])
        : "r"(a0), "r"(a1), "r"(a2), "r"(a3), "r"(b0), "r"(b1));
}
#define FU(x) __float_as_uint(x)

// ---------------- projection GEMM (tf32 mma): Y = X @ W^T + b ----------------
// tile 128(m) x 64(n), K=768 in 12 chunks of 64. Block 256 thr = 8 warps.
// Fragment loads are float2: pairing a0=Q[r0][2c4],a2=Q[r0][2c4+1] with
// b0=W[n][2c4],b1=W[n][2c4+1] — consistent A/B k-pairing, math unchanged.
template <int DEST>
__global__ void __launch_bounds__(256, 3) projmma_kernel(
    const float* __restrict__ Xin, const float* __restrict__ W,
    const float* __restrict__ bias, float* __restrict__ Yout)
{
    extern __shared__ float sm[];
    float* Xs = sm;              // [128][SP]
    float* Ws = sm + 128 * SP;   // [64][SP]
    const float* X = (DEST == 3) ? (const float*)g_att : Xin;

    int tid = threadIdx.x;
    int warp = tid >> 5, lane = tid & 31, g = lane >> 2, c4 = lane & 3;
    int m0 = blockIdx.y * 128, n0 = blockIdx.x * 64;
    int r0 = warp * 16 + g, r1 = r0 + 8;

    float acc[8][4] = {};

    for (int k0 = 0; k0 < CC; k0 += 64) {
        __syncthreads();
        #pragma unroll
        for (int i = 0; i < 8; i++) {                 // X: 128x64 = 2048 float4
            int idx = tid + i * 256;
            int row = idx >> 4, j = idx & 15;
            float4 v = *(const float4*)(X + (size_t)(m0 + row) * CC + k0 + 4 * j);
            float4 t = make_float4(f2tf(v.x), f2tf(v.y), f2tf(v.z), f2tf(v.w));
            *(float4*)(Xs + row * SP + 4 * j) = t;
        }
        #pragma unroll
        for (int i = 0; i < 4; i++) {                 // W: 64x64 = 1024 float4
            int idx = tid + i * 256;
            int row = idx >> 4, j = idx & 15;
            float4 v = *(const float4*)(W + (size_t)(n0 + row) * CC + k0 + 4 * j);
            float4 t = make_float4(f2tf(v.x), f2tf(v.y), f2tf(v.z), f2tf(v.w));
            *(float4*)(Ws + row * SP + 4 * j) = t;
        }
        __syncthreads();

        #pragma unroll
        for (int s = 0; s < 8; s++) {
            int kb = 8 * s + 2 * c4;
            float2 a0 = *(const float2*)(Xs + r0 * SP + kb);
            float2 a1 = *(const float2*)(Xs + r1 * SP + kb);
            #pragma unroll
            for (int n = 0; n < 8; n++) {
                float2 b = *(const float2*)(Ws + (8 * n + g) * SP + kb);
                mma8(acc[n], FU(a0.x), FU(a1.x), FU(a0.y), FU(a1.y),
                     FU(b.x), FU(b.y));
            }
        }
    }

    #pragma unroll
    for (int n = 0; n < 8; n++) {
        int col = n0 + 8 * n + 2 * c4;
        float b0v = bias[col], b1v = bias[col + 1];
        float2 v0 = make_float2(acc[n][0] + b0v, acc[n][1] + b1v);
        float2 v1 = make_float2(acc[n][2] + b0v, acc[n][3] + b1v);
        int mr0 = m0 + r0, mr1 = m0 + r1;
        if (DEST == 0) {
            *(float2*)(g_Q + ((size_t)(col >> 6) * HW + mr0) * HD + (col & 63)) = v0;
            *(float2*)(g_Q + ((size_t)(col >> 6) * HW + mr1) * HD + (col & 63)) = v1;
        } else if (DEST == 1) {
            *(float2*)(g_K + ((size_t)(col >> 6) * HW + mr0) * HD + (col & 63)) = v0;
            *(float2*)(g_K + ((size_t)(col >> 6) * HW + mr1) * HD + (col & 63)) = v1;
        } else if (DEST == 2) {
            *(float2*)(g_V + ((size_t)(col >> 6) * HW + mr0) * HD + (col & 63)) = v0;
            *(float2*)(g_V + ((size_t)(col >> 6) * HW + mr1) * HD + (col & 63)) = v1;
        } else {
            *(float2*)(Yout + (size_t)mr0 * CC + col) = v0;
            *(float2*)(Yout + (size_t)mr1 * CC + col) = v1;
        }
    }
}

// ---------------- decomposed rel-pos bias (FFMA, small) ----------------------
__global__ void __launch_bounds__(256) relpos_kernel(
    const float* __restrict__ rph, const float* __restrict__ rpw)
{
    __shared__ float Qs[64][65];
    __shared__ float Rs[64][65];
    int axis = blockIdx.z, head = blockIdx.y, a0 = blockIdx.x;
    int tid = threadIdx.x, tx = tid & 15, ty = tid >> 4;
    int lr = tid >> 2, lc = (tid & 3) * 4;

    int tok_l = (axis == 0) ? (a0 * 64 + lr) : (lr * 64 + a0);
    const float* rp = (axis == 0) ? rph : rpw;
    #pragma unroll
    for (int c0 = 0; c0 < 64; c0 += 16) {
        int c = lc + c0;
        float4 qv = *(const float4*)&g_Q[((size_t)head * HW + tok_l) * HD + c];
        Qs[lr][c + 0] = qv.x; Qs[lr][c + 1] = qv.y;
        Qs[lr][c + 2] = qv.z; Qs[lr][c + 3] = qv.w;
        float4 rv = *(const float4*)&rp[(size_t)(a0 - lr + 63) * HD + c];
        Rs[lr][c + 0] = rv.x; Rs[lr][c + 1] = rv.y;
        Rs[lr][c + 2] = rv.z; Rs[lr][c + 3] = rv.w;
    }
    __syncthreads();

    float acc[4][4] = {};
    #pragma unroll
    for (int d = 0; d < 64; d++) {
        float a[4], b[4];
        #pragma unroll
        for (int i = 0; i < 4; i++) a[i] = Qs[ty + i * 16][d];
        #pragma unroll
        for (int j = 0; j < 4; j++) b[j] = Rs[tx + j * 16][d];
        #pragma unroll
        for (int i = 0; i < 4; i++)
            #pragma unroll
            for (int j = 0; j < 4; j++)
                acc[i][j] = fmaf(a[i], b[j], acc[i][j]);
    }

    #pragma unroll
    for (int i = 0; i < 4; i++) {
        int r = ty + i * 16;
        int tok = (axis == 0) ? (a0 * 64 + r) : (r * 64 + a0);
        #pragma unroll
        for (int j = 0; j < 4; j++) {
            int k = tx + j * 16;
            if (axis == 0)
                g_relh[((size_t)head * HD + k) * HW + tok] = acc[i][j];
            else
                g_relw[((size_t)head * HW + tok) * HD + k] = acc[i][j];
        }
    }
}

// ---------------- flash attention, tf32 mma, P in registers ------------------
// q-tile 128, key-tile 64. 8 warps; warp w owns q rows 16w..16w+15 x 64 keys.
// smem 102.5KB -> 2 CTAs/SM. P feeds PV mma directly from S registers:
// a0=S[s][0](r0,key 2c4) pairs b0=V[key 2c4][d]; a2=S[s][1] pairs b1.
__global__ void __launch_bounds__(256, 2) attnmma_kernel()
{
    extern __shared__ float sm[];
    float* Qs  = sm;                  // [128][SP] tf32, prescaled by 0.125
    float* Ks  = Qs + 128 * SP;       // [64][SP]  tf32
    float* Vt  = Ks + 64 * SP;        // [64][SP]  tf32, TRANSPOSED: [d][key]
    float* Bws = Vt + 64 * SP;        // [128][SP] f32 rel_w bias
    float* Bhs = Bws + 128 * SP;      // [128] f32 rel_h column for this key tile

    int tid = threadIdx.x;
    int warp = tid >> 5, lane = tid & 31, g = lane >> 2, c4 = lane & 3;
    int head = blockIdx.y, q0 = blockIdx.x * 128;
    int r0 = warp * 16 + g, r1 = r0 + 8;

    size_t qb = (size_t)head * HW + q0;
    #pragma unroll
    for (int i = 0; i < 8; i++) {
        int idx = tid + i * 256;
        int row = idx >> 4, j = idx & 15;
        float4 v = *(const float4*)(g_Q + (qb + row) * HD + 4 * j);
        float4 t = make_float4(f2tf(v.x * 0.125f), f2tf(v.y * 0.125f),
                               f2tf(v.z * 0.125f), f2tf(v.w * 0.125f));
        *(float4*)(Qs + row * SP + 4 * j) = t;
        float4 w = *(const float4*)(g_relw + (qb + row) * HD + 4 * j);
        *(float4*)(Bws + row * SP + 4 * j) = w;
    }

    float O[8][4] = {};
    float m0r = -INFINITY, m1r = -INFINITY, l0 = 0.f, l1 = 0.f;

    for (int kt = 0; kt < HW / 64; kt++) {
        __syncthreads();  // previous iter's Ks/Vt/Bhs readers done
        size_t kb = (size_t)head * HW + kt * 64;
        #pragma unroll
        for (int i = 0; i < 4; i++) {                 // K: coalesced, direct
            int idx = tid + i * 256;
            int row = idx >> 4, j = idx & 15;
            float4 v = *(const float4*)(g_K + (kb + row) * HD + 4 * j);
            float4 t = make_float4(f2tf(v.x), f2tf(v.y), f2tf(v.z), f2tf(v.w));
            *(float4*)(Ks + row * SP + 4 * j) = t;
        }
        #pragma unroll
        for (int i = 0; i < 4; i++) {                 // V: transpose-scatter
            int idx = tid + i * 256;
            int key = idx & 63, j = idx >> 6;
            float4 v = *(const float4*)(g_V + (kb + key) * HD + 4 * j);
            Vt[(4 * j + 0) * SP + key] = f2tf(v.x);
            Vt[(4 * j + 1) * SP + key] = f2tf(v.y);
            Vt[(4 * j + 2) * SP + key] = f2tf(v.z);
            Vt[(4 * j + 3) * SP + key] = f2tf(v.w);
        }
        if (tid < 128)
            Bhs[tid] = g_relh[((size_t)head * HD + kt) * HW + q0 + tid];
        __syncthreads();

        // ---- S = (Q/8) @ K^T + bias ----
        float S[8][4];
        float bh0 = Bhs[r0], bh1 = Bhs[r1];
        #pragma unroll
        for (int n = 0; n < 8; n++) {
            int col = 8 * n + 2 * c4;
            float2 w0 = *(const float2*)(Bws + r0 * SP + col);
            float2 w1 = *(const float2*)(Bws + r1 * SP + col);
            S[n][0] = bh0 + w0.x; S[n][1] = bh0 + w0.y;
            S[n][2] = bh1 + w1.x; S[n][3] = bh1 + w1.y;
        }
        #pragma unroll
        for (int s = 0; s < 8; s++) {
            int kb8 = 8 * s + 2 * c4;
            float2 a0 = *(const float2*)(Qs + r0 * SP + kb8);
            float2 a1 = *(const float2*)(Qs + r1 * SP + kb8);
            #pragma unroll
            for (int n = 0; n < 8; n++) {
                float2 b = *(const float2*)(Ks + (8 * n + g) * SP + kb8);
                mma8(S[n], FU(a0.x), FU(a1.x), FU(a0.y), FU(a1.y),
                     FU(b.x), FU(b.y));
            }
        }

        // ---- online softmax (rows private to quad) ----
        float mx0 = -INFINITY, mx1 = -INFINITY;
        #pragma unroll
        for (int n = 0; n < 8; n++) {
            mx0 = fmaxf(mx0, fmaxf(S[n][0], S[n][1]));
            mx1 = fmaxf(mx1, fmaxf(S[n][2], S[n][3]));
        }
        mx0 = fmaxf(mx0, __shfl_xor_sync(0xffffffffu, mx0, 1));
        mx0 = fmaxf(mx0, __shfl_xor_sync(0xffffffffu, mx0, 2));
        mx1 = fmaxf(mx1, __shfl_xor_sync(0xffffffffu, mx1, 1));
        mx1 = fmaxf(mx1, __shfl_xor_sync(0xffffffffu, mx1, 2));
        float nm0 = fmaxf(m0r, mx0), nm1 = fmaxf(m1r, mx1);
        float al0 = __expf(m0r - nm0), al1 = __expf(m1r - nm1);
        m0r = nm0; m1r = nm1;
        float s0 = 0.f, s1 = 0.f;
        #pragma unroll
        for (int n = 0; n < 8; n++) {
            float p00 = f2tf(__expf(S[n][0] - nm0));
            float p01 = f2tf(__expf(S[n][1] - nm0));
            float p10 = f2tf(__expf(S[n][2] - nm1));
            float p11 = f2tf(__expf(S[n][3] - nm1));
            s0 += p00 + p01; s1 += p10 + p11;
            S[n][0] = p00; S[n][1] = p01; S[n][2] = p10; S[n][3] = p11;
            O[n][0] *= al0; O[n][1] *= al0; O[n][2] *= al1; O[n][3] *= al1;
        }
        s0 += __shfl_xor_sync(0xffffffffu, s0, 1);
        s0 += __shfl_xor_sync(0xffffffffu, s0, 2);
        s1 += __shfl_xor_sync(0xffffffffu, s1, 1);
        s1 += __shfl_xor_sync(0xffffffffu, s1, 2);
        l0 = l0 * al0 + s0;
        l1 = l1 * al1 + s1;

        // ---- O += P @ V : A-frags directly from S registers ----
        // a0=P[r0][8s+2c4], a1=P[r1][8s+2c4], a2=P[r0][8s+2c4+1], a3=P[r1][..+1]
        // b = float2 Vt[d=8n+g][keys 8s+2c4, 8s+2c4+1] — consistent pairing.
        #pragma unroll
        for (int s = 0; s < 8; s++) {
            uint32_t a0 = FU(S[s][0]), a1 = FU(S[s][2]);
            uint32_t a2 = FU(S[s][1]), a3 = FU(S[s][3]);
            int kb8 = 8 * s + 2 * c4;
            #pragma unroll
            for (int n = 0; n < 8; n++) {
                float2 b = *(const float2*)(Vt + (8 * n + g) * SP + kb8);
                mma8(O[n], a0, a1, a2, a3, FU(b.x), FU(b.y));
            }
        }
    }

    float inv0 = 1.0f / l0, inv1 = 1.0f / l1;
    #pragma unroll
    for (int n = 0; n < 8; n++) {
        int d = 8 * n + 2 * c4;
        *(float2*)(g_att + (size_t)(q0 + r0) * CC + head * HD + d) =
            make_float2(O[n][0] * inv0, O[n][1] * inv0);
        *(float2*)(g_att + (size_t)(q0 + r1) * CC + head * HD + d) =
            make_float2(O[n][2] * inv1, O[n][3] * inv1);
    }
}

// ---------------- launch -----------------------------------------------------
extern "C" void kernel_launch(void* const* d_in, const int* in_sizes, int n_in,
                              void* d_out, int out_size)
{
    const float* hs  = (const float*)d_in[0];
    const float* w_q = (const float*)d_in[1];
    const float* b_q = (const float*)d_in[2];
    const float* w_k = (const float*)d_in[3];
    const float* b_k = (const float*)d_in[4];
    const float* w_v = (const float*)d_in[5];
    const float* b_v = (const float*)d_in[6];
    const float* w_o = (const float*)d_in[7];
    const float* b_o = (const float*)d_in[8];
    const float* rph = (const float*)d_in[9];
    const float* rpw = (const float*)d_in[10];
    float* out = (float*)d_out;

    int proj_smem = (128 * SP + 64 * SP) * (int)sizeof(float);           // 52224 B
    int att_smem  = (128 * SP + 64 * SP * 2 + 128 * SP + 128) * (int)sizeof(float);  // 104960 B

    cudaFuncSetAttribute(projmma_kernel<0>, cudaFuncAttributeMaxDynamicSharedMemorySize, proj_smem);
    cudaFuncSetAttribute(projmma_kernel<1>, cudaFuncAttributeMaxDynamicSharedMemorySize, proj_smem);
    cudaFuncSetAttribute(projmma_kernel<2>, cudaFuncAttributeMaxDynamicSharedMemorySize, proj_smem);
    cudaFuncSetAttribute(projmma_kernel<3>, cudaFuncAttributeMaxDynamicSharedMemorySize, proj_smem);
    cudaFuncSetAttribute(attnmma_kernel, cudaFuncAttributeMaxDynamicSharedMemorySize, att_smem);

    dim3 gproj(CC / 64, HW / 128);  // (12, 32)
    projmma_kernel<0><<<gproj, 256, proj_smem>>>(hs, w_q, b_q, nullptr);
    projmma_kernel<1><<<gproj, 256, proj_smem>>>(hs, w_k, b_k, nullptr);
    projmma_kernel<2><<<gproj, 256, proj_smem>>>(hs, w_v, b_v, nullptr);

    relpos_kernel<<<dim3(64, NHEADS, 2), 256>>>(rph, rpw);

    attnmma_kernel<<<dim3(HW / 128, NHEADS), 256, att_smem>>>();

    projmma_kernel<3><<<gproj, 256, proj_smem>>>(nullptr, w_o, b_o, out);
}